// round 13
// baseline (speedup 1.0000x reference)
#include <cuda_runtime.h>
#include <cuda_fp16.h>
#include <cstdint>

#define WIN 49
#define HEADS 12
#define HD 32
#define DIMC 384
#define BATCH 4096
#define NWIN 64
#define QKVC (3 * DIMC)     // 1152
#define MROWS (BATCH * WIN) // 200704
#define KTOT 384

// ---------------- scratch (allocation-free rule: __device__ globals) -------
__device__ __half g_x16[(size_t)MROWS * KTOT];
__device__ __half g_qkv[(size_t)MROWS * QKVC];
__device__ __half g_att[(size_t)MROWS * DIMC];
__device__ __half g_wqkv_hi[QKVC * KTOT];
__device__ __half g_wprj_hi[DIMC * KTOT];
__device__ float  g_bm[(size_t)NWIN * HEADS * WIN * WIN]; // mask+bias combined

// ---------------- helpers ---------------------------------------------------
__device__ __forceinline__ uint32_t smem_u32(const void* p) {
    uint32_t a;
    asm("{ .reg .u64 t; cvta.to.shared.u64 t, %1; cvt.u32.u64 %0, t; }" : "=r"(a) : "l"(p));
    return a;
}
__device__ __forceinline__ uint32_t pack2_f16(float even, float odd) {
    uint32_t r;
    asm("cvt.rn.f16x2.f32 %0, %1, %2;" : "=r"(r) : "f"(odd), "f"(even));
    return r;
}
__device__ __forceinline__ void ldmx4(uint32_t& r0, uint32_t& r1, uint32_t& r2, uint32_t& r3,
                                      uint32_t addr) {
    asm volatile("ldmatrix.sync.aligned.m8n8.x4.shared.b16 {%0,%1,%2,%3}, [%4];"
                 : "=r"(r0), "=r"(r1), "=r"(r2), "=r"(r3) : "r"(addr));
}
__device__ __forceinline__ void ldmx4t(uint32_t& r0, uint32_t& r1, uint32_t& r2, uint32_t& r3,
                                       uint32_t addr) {
    asm volatile("ldmatrix.sync.aligned.m8n8.x4.trans.shared.b16 {%0,%1,%2,%3}, [%4];"
                 : "=r"(r0), "=r"(r1), "=r"(r2), "=r"(r3) : "r"(addr));
}
// fp32-accumulate (attention)
__device__ __forceinline__ void mma16816(float* d, uint32_t a0, uint32_t a1, uint32_t a2,
                                         uint32_t a3, uint32_t b0, uint32_t b1) {
    asm volatile(
        "mma.sync.aligned.m16n8k16.row.col.f32.f16.f16.f32 "
        "{%0,%1,%2,%3}, {%4,%5,%6,%7}, {%8,%9}, {%0,%1,%2,%3};"
        : "+f"(d[0]), "+f"(d[1]), "+f"(d[2]), "+f"(d[3])
        : "r"(a0), "r"(a1), "r"(a2), "r"(a3), "r"(b0), "r"(b1));
}
// fp16-accumulate (GEMM inner chains of 2 MMAs)
__device__ __forceinline__ void mma16816h(uint32_t* d, uint32_t a0, uint32_t a1, uint32_t a2,
                                          uint32_t a3, uint32_t b0, uint32_t b1) {
    asm volatile(
        "mma.sync.aligned.m16n8k16.row.col.f16.f16.f16.f16 "
        "{%0,%1}, {%2,%3,%4,%5}, {%6,%7}, {%0,%1};"
        : "+r"(d[0]), "+r"(d[1])
        : "r"(a0), "r"(a1), "r"(a2), "r"(a3), "r"(b0), "r"(b1));
}
__device__ __forceinline__ void cp_async16(uint32_t saddr, const void* gaddr) {
    asm volatile("cp.async.cg.shared.global [%0], [%1], 16;" :: "r"(saddr), "l"(gaddr) : "memory");
}

// ---------------------------------------------------------------------------
// prep kernels
// ---------------------------------------------------------------------------
__global__ void prep_x_kernel(const float* __restrict__ X, __half* __restrict__ Y) {
    size_t idx = (size_t)blockIdx.x * 256 + threadIdx.x;
    float4 f = *(const float4*)(X + idx * 4);
    uint32_t h0 = pack2_f16(f.x, f.y), h1 = pack2_f16(f.z, f.w);
    *(uint2*)(Y + idx * 4) = make_uint2(h0, h1);
}

__global__ void prep_w_kernel(const float* __restrict__ W,
                              __half* __restrict__ hi, int K, int N) {
    int idx = blockIdx.x * 256 + threadIdx.x;
    if (idx >= K * N) return;
    int k = idx / N, n = idx % N;
    hi[(size_t)n * K + k] = __float2half_rn(W[idx]);
}

__global__ void prep_bm_kernel(const float* __restrict__ mask,
                               const float* __restrict__ bias_table,
                               const int* __restrict__ rel_index,
                               float* __restrict__ bm) {
    int idx = blockIdx.x * 256 + threadIdx.x;
    if (idx >= NWIN * HEADS * WIN * WIN) return;
    int rc = idx % (WIN * WIN);
    int nwh = idx / (WIN * WIN);
    int h = nwh % HEADS, nw = nwh / HEADS;
    bm[idx] = mask[nw * WIN * WIN + rc] + bias_table[rel_index[rc] * HEADS + h];
}

// ---------------------------------------------------------------------------
// Tile geometry (GEMMs)
// ---------------------------------------------------------------------------
#define BM 128
#define BN 128
#define KC 64
#define NCHUNK (KTOT / KC)
#define PITCHB 144
#define TILEB (128 * PITCHB)

#define GM_STAGE (2 * TILEB)
#define GM_SMEM (2 * GM_STAGE)

#define GM_ISSUE(stg, k0, Abase, Bhi, bn)                                        \
    do {                                                                         \
        _Pragma("unroll")                                                        \
        for (int i = 0; i < 8; i++) {                                            \
            int g = tid + 256 * i;                                               \
            int sel = g >> 10;                                                   \
            int r = g & 1023;                                                    \
            int row = r >> 3, k8 = r & 7;                                        \
            const __half* src = (sel ? (Bhi) + (size_t)((bn) + row) * KTOT       \
                                     : (Abase) + (size_t)row * KTOT) + (k0) + k8 * 8; \
            cp_async16((stg) + sel * TILEB + row * PITCHB + k8 * 16, src);       \
        }                                                                        \
        asm volatile("cp.async.commit_group;" ::: "memory");                     \
    } while (0)

// GEMM mainloop: f16-acc MMA chains of 2, promoted to fp32 master acc[4][4][4].
// Warp tiles processed in two mt-groups of 8 tiles to bound register pressure.
#define GM_MAINLOOP(Abase, Bhi, bn)                                              \
    GM_ISSUE(sb, 0, Abase, Bhi, bn);                                             \
    for (int c = 0; c < NCHUNK; c++) {                                           \
        const uint32_t sp = sb + (uint32_t)(c & 1) * GM_STAGE;                   \
        const bool pf = (c + 1 < NCHUNK);                                        \
        if (pf) GM_ISSUE(sb + (uint32_t)((c + 1) & 1) * GM_STAGE, (c + 1) * KC, Abase, Bhi, bn); \
        if (pf) { asm volatile("cp.async.wait_group 1;" ::: "memory"); }         \
        else    { asm volatile("cp.async.wait_group 0;" ::: "memory"); }         \
        __syncthreads();                                                         \
        _Pragma("unroll")                                                        \
        for (int gidx = 0; gidx < 2; gidx++) {                                   \
            uint32_t cacc[2][4][2];                                              \
            _Pragma("unroll")                                                    \
            for (int mi = 0; mi < 2; mi++)                                       \
                _Pragma("unroll")                                                \
                for (int nt = 0; nt < 4; nt++) { cacc[mi][nt][0] = 0u; cacc[mi][nt][1] = 0u; } \
            _Pragma("unroll")                                                    \
            for (int kk = 0; kk < 4; kk++) {                                     \
                const uint32_t kbyte = kk * 32;                                  \
                uint32_t Ar[2][4], Bh[2][4];                                     \
                _Pragma("unroll")                                                \
                for (int mi = 0; mi < 2; mi++) {                                 \
                    const int mt = 2 * gidx + mi;                                \
                    ldmx4(Ar[mi][0], Ar[mi][1], Ar[mi][2], Ar[mi][3],            \
                          sp + (wm * 64 + mt * 16 + a_r) * PITCHB + kbyte + a_c);\
                }                                                                \
                _Pragma("unroll")                                                \
                for (int p = 0; p < 2; p++)                                      \
                    ldmx4(Bh[p][0], Bh[p][1], Bh[p][2], Bh[p][3],                \
                          sp + TILEB + (wn * 32 + p * 16 + b_noff) * PITCHB + kbyte + b_koff); \
                _Pragma("unroll")                                                \
                for (int mi = 0; mi < 2; mi++)                                   \
                    _Pragma("unroll")                                            \
                    for (int nt = 0; nt < 4; nt++) {                             \
                        const int p = nt >> 1, hh = (nt & 1) * 2;                \
                        mma16816h(cacc[mi][nt], Ar[mi][0], Ar[mi][1], Ar[mi][2], Ar[mi][3], \
                                  Bh[p][hh], Bh[p][hh + 1]);                     \
                    }                                                            \
                if (kk & 1) {                                                    \
                    _Pragma("unroll")                                            \
                    for (int mi = 0; mi < 2; mi++)                               \
                        _Pragma("unroll")                                        \
                        for (int nt = 0; nt < 4; nt++) {                         \
                            float2 lo = __half22float2(*(__half2*)&cacc[mi][nt][0]); \
                            float2 hi = __half22float2(*(__half2*)&cacc[mi][nt][1]); \
                            acc[2 * gidx + mi][nt][0] += lo.x;                   \
                            acc[2 * gidx + mi][nt][1] += lo.y;                   \
                            acc[2 * gidx + mi][nt][2] += hi.x;                   \
                            acc[2 * gidx + mi][nt][3] += hi.y;                   \
                            cacc[mi][nt][0] = 0u; cacc[mi][nt][1] = 0u;          \
                        }                                                        \
                }                                                                \
            }                                                                    \
        }                                                                        \
        __syncthreads();                                                         \
    }

// ---------------------------------------------------------------------------
// qkv GEMM: 1-term fp16, chunk-promoted f16 acc; C fp16 (q scaled)
// ---------------------------------------------------------------------------
__global__ __launch_bounds__(256, 2)
void qkv_gemm_kernel(const __half* __restrict__ A,
                     const __half* __restrict__ Bhi,
                     const float* __restrict__ bias, __half* __restrict__ C) {
    extern __shared__ char smem[];
    const uint32_t sb = smem_u32(smem);
    const int tid = threadIdx.x;
    const int warp = tid >> 5, lane = tid & 31;
    const int wm = warp >> 2, wn = warp & 3;
    const int bm = blockIdx.y * BM, bn = blockIdx.x * BN;

    float acc[4][4][4];
#pragma unroll
    for (int i = 0; i < 4; i++)
#pragma unroll
        for (int j = 0; j < 4; j++)
#pragma unroll
            for (int r = 0; r < 4; r++) acc[i][j][r] = 0.f;

    const __half* Abase = A + (size_t)bm * KTOT;
    const int a_r = lane & 15;
    const int a_c = (lane >> 4) * 16;
    const int b_lrow = lane & 7;
    const int b_q = lane >> 3;
    const int b_noff = ((b_q >> 1) * 8) + b_lrow;
    const int b_koff = (b_q & 1) * 16;

    GM_MAINLOOP(Abase, Bhi, bn)

    const int gid = lane >> 2, tig = lane & 3;
    const float qscale = 0.17677669529663687f;
#pragma unroll
    for (int mt = 0; mt < 4; mt++) {
        const int row = bm + wm * 64 + mt * 16 + gid;
#pragma unroll
        for (int nt = 0; nt < 4; nt++) {
            const int col = bn + wn * 32 + nt * 8 + tig * 2;
            const float b0 = bias[col], b1 = bias[col + 1];
            const float s = (col < DIMC) ? qscale : 1.0f;
            __half2 v0 = __floats2half2_rn((acc[mt][nt][0] + b0) * s, (acc[mt][nt][1] + b1) * s);
            __half2 v1 = __floats2half2_rn((acc[mt][nt][2] + b0) * s, (acc[mt][nt][3] + b1) * s);
            *(__half2*)(C + (size_t)row * QKVC + col) = v0;
            *(__half2*)(C + (size_t)(row + 8) * QKVC + col) = v1;
        }
    }
}

// ---------------------------------------------------------------------------
// proj GEMM: 1-term fp16, chunk-promoted f16 acc; C fp32
// ---------------------------------------------------------------------------
__global__ __launch_bounds__(256, 2)
void proj_gemm_kernel(const __half* __restrict__ A,
                      const __half* __restrict__ Bhi,
                      const float* __restrict__ bias, float* __restrict__ C) {
    extern __shared__ char smem[];
    const uint32_t sb = smem_u32(smem);
    const int tid = threadIdx.x;
    const int warp = tid >> 5, lane = tid & 31;
    const int wm = warp >> 2, wn = warp & 3;
    const int bm = blockIdx.y * BM, bn = blockIdx.x * BN;

    float acc[4][4][4];
#pragma unroll
    for (int i = 0; i < 4; i++)
#pragma unroll
        for (int j = 0; j < 4; j++)
#pragma unroll
            for (int r = 0; r < 4; r++) acc[i][j][r] = 0.f;

    const __half* Abase = A + (size_t)bm * KTOT;
    const int a_r = lane & 15;
    const int a_c = (lane >> 4) * 16;
    const int b_lrow = lane & 7;
    const int b_q = lane >> 3;
    const int b_noff = ((b_q >> 1) * 8) + b_lrow;
    const int b_koff = (b_q & 1) * 16;

    GM_MAINLOOP(Abase, Bhi, bn)

    const int gid = lane >> 2, tig = lane & 3;
#pragma unroll
    for (int mt = 0; mt < 4; mt++) {
        const int row = bm + wm * 64 + mt * 16 + gid;
#pragma unroll
        for (int nt = 0; nt < 4; nt++) {
            const int col = bn + wn * 32 + nt * 8 + tig * 2;
            const float b0 = bias[col], b1 = bias[col + 1];
            float2 v0 = make_float2(acc[mt][nt][0] + b0, acc[mt][nt][1] + b1);
            float2 v1 = make_float2(acc[mt][nt][2] + b0, acc[mt][nt][3] + b1);
            *(float2*)(C + (size_t)row * DIMC + col) = v0;
            *(float2*)(C + (size_t)(row + 8) * DIMC + col) = v1;
        }
    }
}

// ---------------------------------------------------------------------------
// Tensor-core attention, amortized (unchanged, fp32 accumulate)
// ---------------------------------------------------------------------------
#define AQ_PITCH 80
#define ATN_TEN (64 * AQ_PITCH)
#define ATN_STAGE (3 * ATN_TEN)
#define BI_PITCH 66
#define GRP 8

__global__ __launch_bounds__(128)
void attn_mma_kernel(const __half* __restrict__ qkv,
                     const float* __restrict__ bm,
                     __half* __restrict__ out) {
    __shared__ __align__(16) char sm[2 * ATN_STAGE + 64 * BI_PITCH * 4];
    const uint32_t sb = smem_u32(sm);
    const uint32_t sBI = sb + 2 * ATN_STAGE;

    const int nw = blockIdx.x, h = blockIdx.y;
    const int tid = threadIdx.x;
    const int warp = tid >> 5, lane = tid & 31;
    const int gid = lane >> 2, tig = lane & 3;
    const int row0 = 16 * warp + gid;

    const float* bmrow = bm + (size_t)(nw * HEADS + h) * (WIN * WIN);
    for (int idx = tid; idx < 64 * 64; idx += 128) {
        int r = idx >> 6, c = idx & 63;
        float v = 0.f;
        if (r < WIN) v = (c < WIN) ? bmrow[r * WIN + c] : -1e30f;
        asm volatile("st.shared.b32 [%0], %1;"
                     :: "r"(sBI + (uint32_t)(r * BI_PITCH + c) * 4), "f"(v) : "memory");
    }
    for (int idx = tid; idx < 450; idx += 128) {
        int st = idx / 225, rem = idx % 225;
        int t = rem / 75, r2 = rem % 75;
        int row = 49 + r2 / 5, ch = r2 % 5;
        asm volatile("st.shared.v4.b32 [%0], {%1,%1,%1,%1};"
                     :: "r"(sb + st * ATN_STAGE + t * ATN_TEN + row * AQ_PITCH + ch * 16),
                        "r"(0) : "memory");
    }
    __syncthreads();

    float Sb[8][4];
#pragma unroll
    for (int nt = 0; nt < 8; nt++) {
        const uint32_t col4 = (uint32_t)(8 * nt + 2 * tig) * 4;
        asm volatile("ld.shared.v2.f32 {%0,%1}, [%2];" : "=f"(Sb[nt][0]), "=f"(Sb[nt][1])
                     : "r"(sBI + (uint32_t)row0 * BI_PITCH * 4 + col4));
        asm volatile("ld.shared.v2.f32 {%0,%1}, [%2];" : "=f"(Sb[nt][2]), "=f"(Sb[nt][3])
                     : "r"(sBI + (uint32_t)(row0 + 8) * BI_PITCH * 4 + col4));
    }

    const int a_r = lane & 15;
    const int a_c = (lane >> 4) * 16;
    const int b_lrow = lane & 7;
    const int b_q = lane >> 3;
    const int b_noff = (b_q >> 1) * 8 + b_lrow;
    const int b_koff = (b_q & 1) * 16;
    const uint32_t v_row = (uint32_t)((lane & 7) + 8 * ((lane >> 3) & 1));
    const uint32_t v_cb  = (uint32_t)((lane >> 4) * 16);

    const int img0 = blockIdx.z * GRP;

#define AT_ISSUE(stg, ii)                                                         \
    do {                                                                          \
        const __half* base_ = qkv + ((size_t)((img0 + (ii)) * NWIN + nw) * WIN) * QKVC + h * HD; \
        _Pragma("unroll")                                                         \
        for (int u = 0; u < 5; u++) {                                             \
            int idx = tid + 128 * u;                                              \
            if (idx < 588) {                                                      \
                int i = idx / 12, rem = idx % 12;                                 \
                int sel = rem >> 2, ch = rem & 3;                                 \
                cp_async16((stg) + sel * ATN_TEN + i * AQ_PITCH + ch * 16,        \
                           base_ + (size_t)i * QKVC + sel * DIMC + ch * 8);       \
            }                                                                     \
        }                                                                         \
        asm volatile("cp.async.commit_group;" ::: "memory");                      \
    } while (0)

    AT_ISSUE(sb, 0);

    for (int ii = 0; ii < GRP; ii++) {
        const uint32_t sp = sb + (uint32_t)(ii & 1) * ATN_STAGE;
        const uint32_t sQ = sp, sK = sp + ATN_TEN, sV = sp + 2 * ATN_TEN;
        const bool pf = (ii + 1 < GRP);
        if (pf) AT_ISSUE(sb + (uint32_t)((ii + 1) & 1) * ATN_STAGE, ii + 1);
        if (pf) { asm volatile("cp.async.wait_group 1;" ::: "memory"); }
        else    { asm volatile("cp.async.wait_group 0;" ::: "memory"); }
        __syncthreads();

        uint32_t Aq[2][4];
#pragma unroll
        for (int t = 0; t < 2; t++)
            ldmx4(Aq[t][0], Aq[t][1], Aq[t][2], Aq[t][3],
                  sQ + (16 * warp + a_r) * AQ_PITCH + t * 32 + a_c);

        float S[8][4];
#pragma unroll
        for (int nt = 0; nt < 8; nt++)
#pragma unroll
            for (int r = 0; r < 4; r++) S[nt][r] = Sb[nt][r];

#pragma unroll
        for (int p = 0; p < 4; p++)
#pragma unroll
            for (int t = 0; t < 2; t++) {
                uint32_t Bk[4];
                ldmx4(Bk[0], Bk[1], Bk[2], Bk[3],
                      sK + (16 * p + b_noff) * AQ_PITCH + t * 32 + b_koff);
                mma16816(S[2 * p],     Aq[t][0], Aq[t][1], Aq[t][2], Aq[t][3], Bk[0], Bk[1]);
                mma16816(S[2 * p + 1], Aq[t][0], Aq[t][1], Aq[t][2], Aq[t][3], Bk[2], Bk[3]);
            }

        float m0 = -3.0e38f, m1 = -3.0e38f;
#pragma unroll
        for (int nt = 0; nt < 8; nt++) {
            m0 = fmaxf(m0, fmaxf(S[nt][0], S[nt][1]));
            m1 = fmaxf(m1, fmaxf(S[nt][2], S[nt][3]));
        }
        m0 = fmaxf(m0, __shfl_xor_sync(0xffffffffu, m0, 1));
        m0 = fmaxf(m0, __shfl_xor_sync(0xffffffffu, m0, 2));
        m1 = fmaxf(m1, __shfl_xor_sync(0xffffffffu, m1, 1));
        m1 = fmaxf(m1, __shfl_xor_sync(0xffffffffu, m1, 2));

        float s0 = 0.f, s1 = 0.f;
#pragma unroll
        for (int nt = 0; nt < 8; nt++) {
            S[nt][0] = __expf(S[nt][0] - m0);
            S[nt][1] = __expf(S[nt][1] - m0);
            S[nt][2] = __expf(S[nt][2] - m1);
            S[nt][3] = __expf(S[nt][3] - m1);
            s0 += S[nt][0] + S[nt][1];
            s1 += S[nt][2] + S[nt][3];
        }
        s0 += __shfl_xor_sync(0xffffffffu, s0, 1);
        s0 += __shfl_xor_sync(0xffffffffu, s0, 2);
        s1 += __shfl_xor_sync(0xffffffffu, s1, 1);
        s1 += __shfl_xor_sync(0xffffffffu, s1, 2);
        const float inv0 = 1.0f / s0, inv1 = 1.0f / s1;

        uint32_t P[4][4];
#pragma unroll
        for (int t = 0; t < 4; t++) {
            P[t][0] = pack2_f16(S[2 * t][0], S[2 * t][1]);
            P[t][1] = pack2_f16(S[2 * t][2], S[2 * t][3]);
            P[t][2] = pack2_f16(S[2 * t + 1][0], S[2 * t + 1][1]);
            P[t][3] = pack2_f16(S[2 * t + 1][2], S[2 * t + 1][3]);
        }

        float O[4][4];
#pragma unroll
        for (int i = 0; i < 4; i++)
#pragma unroll
            for (int r = 0; r < 4; r++) O[i][r] = 0.f;

#pragma unroll
        for (int t = 0; t < 4; t++)
#pragma unroll
            for (int g = 0; g < 2; g++) {
                uint32_t Bv[4];
                ldmx4t(Bv[0], Bv[1], Bv[2], Bv[3],
                       sV + (16 * t + v_row) * AQ_PITCH + 32 * g + v_cb);
                mma16816(O[2 * g],     P[t][0], P[t][1], P[t][2], P[t][3], Bv[0], Bv[1]);
                mma16816(O[2 * g + 1], P[t][0], P[t][1], P[t][2], P[t][3], Bv[2], Bv[3]);
            }

        const size_t ob = (size_t)((img0 + ii) * NWIN + nw) * WIN;
#pragma unroll
        for (int nt = 0; nt < 4; nt++) {
            const int col = h * HD + 8 * nt + 2 * tig;
            if (row0 < WIN) {
                __half2 v = __floats2half2_rn(O[nt][0] * inv0, O[nt][1] * inv0);
                *(__half2*)(out + (ob + row0) * DIMC + col) = v;
            }
            if (row0 + 8 < WIN) {
                __half2 v = __floats2half2_rn(O[nt][2] * inv1, O[nt][3] * inv1);
                *(__half2*)(out + (ob + row0 + 8) * DIMC + col) = v;
            }
        }
        __syncthreads();
    }
#undef AT_ISSUE
}

// ---------------------------------------------------------------------------
extern "C" void kernel_launch(void* const* d_in, const int* in_sizes, int n_in,
                              void* d_out, int out_size) {
    const float* x          = (const float*)d_in[0];
    const float* mask       = (const float*)d_in[1];
    const float* qkv_w      = (const float*)d_in[2];
    const float* qkv_b      = (const float*)d_in[3];
    const float* proj_w     = (const float*)d_in[4];
    const float* proj_b     = (const float*)d_in[5];
    const float* bias_table = (const float*)d_in[6];
    const int*   rel_index  = (const int*)d_in[7];
    float* out = (float*)d_out;

    __half *x16, *qkv, *att, *wq_hi, *wp_hi;
    float* bmc;
    cudaGetSymbolAddress((void**)&x16, g_x16);
    cudaGetSymbolAddress((void**)&qkv, g_qkv);
    cudaGetSymbolAddress((void**)&att, g_att);
    cudaGetSymbolAddress((void**)&wq_hi, g_wqkv_hi);
    cudaGetSymbolAddress((void**)&wp_hi, g_wprj_hi);
    cudaGetSymbolAddress((void**)&bmc, g_bm);

    cudaFuncSetAttribute(qkv_gemm_kernel, cudaFuncAttributeMaxDynamicSharedMemorySize, GM_SMEM);
    cudaFuncSetAttribute(proj_gemm_kernel, cudaFuncAttributeMaxDynamicSharedMemorySize, GM_SMEM);

    // 0) preps
    prep_x_kernel<<<(size_t)MROWS * KTOT / 4 / 256, 256>>>(x, x16);
    prep_w_kernel<<<(KTOT * QKVC + 255) / 256, 256>>>(qkv_w, wq_hi, KTOT, QKVC);
    prep_w_kernel<<<(KTOT * DIMC + 255) / 256, 256>>>(proj_w, wp_hi, KTOT, DIMC);
    prep_bm_kernel<<<(NWIN * HEADS * WIN * WIN + 255) / 256, 256>>>(mask, bias_table,
                                                                    rel_index, bmc);
    // 1) qkv GEMM (1-term, chunk-promoted f16 acc)
    {
        dim3 grid(QKVC / BN, MROWS / BM);
        qkv_gemm_kernel<<<grid, 256, GM_SMEM>>>(x16, wq_hi, qkv_b, qkv);
    }
    // 2) tensor-core attention
    {
        dim3 grid(NWIN, HEADS, BATCH / NWIN / GRP);
        attn_mma_kernel<<<grid, 128>>>(qkv, bmc, att);
    }
    // 3) proj GEMM (1-term, chunk-promoted f16 acc)
    {
        dim3 grid(DIMC / BN, MROWS / BM);
        proj_gemm_kernel<<<grid, 256, GM_SMEM>>>(att, wp_hi, proj_b, out);
    }
}

// round 14
// speedup vs baseline: 1.0535x; 1.0535x over previous
#include <cuda_runtime.h>
#include <cuda_fp16.h>
#include <cstdint>

#define WIN 49
#define HEADS 12
#define HD 32
#define DIMC 384
#define BATCH 4096
#define NWIN 64
#define QKVC (3 * DIMC)     // 1152
#define MROWS (BATCH * WIN) // 200704
#define KTOT 384

// ---------------- scratch (allocation-free rule: __device__ globals) -------
__device__ __half g_x16[(size_t)MROWS * KTOT];
__device__ __half g_qkv[(size_t)MROWS * QKVC];
__device__ __half g_att[(size_t)MROWS * DIMC];
__device__ __half g_wqkv_hi[QKVC * KTOT];
__device__ __half g_wprj_hi[DIMC * KTOT];
__device__ float  g_bm[(size_t)NWIN * HEADS * WIN * WIN]; // mask+bias combined

// ---------------- helpers ---------------------------------------------------
__device__ __forceinline__ uint32_t smem_u32(const void* p) {
    uint32_t a;
    asm("{ .reg .u64 t; cvta.to.shared.u64 t, %1; cvt.u32.u64 %0, t; }" : "=r"(a) : "l"(p));
    return a;
}
__device__ __forceinline__ uint32_t pack2_f16(float even, float odd) {
    uint32_t r;
    asm("cvt.rn.f16x2.f32 %0, %1, %2;" : "=r"(r) : "f"(odd), "f"(even));
    return r;
}
__device__ __forceinline__ void ldmx4(uint32_t& r0, uint32_t& r1, uint32_t& r2, uint32_t& r3,
                                      uint32_t addr) {
    asm volatile("ldmatrix.sync.aligned.m8n8.x4.shared.b16 {%0,%1,%2,%3}, [%4];"
                 : "=r"(r0), "=r"(r1), "=r"(r2), "=r"(r3) : "r"(addr));
}
__device__ __forceinline__ void ldmx4t(uint32_t& r0, uint32_t& r1, uint32_t& r2, uint32_t& r3,
                                       uint32_t addr) {
    asm volatile("ldmatrix.sync.aligned.m8n8.x4.trans.shared.b16 {%0,%1,%2,%3}, [%4];"
                 : "=r"(r0), "=r"(r1), "=r"(r2), "=r"(r3) : "r"(addr));
}
// fp32-accumulate (attention)
__device__ __forceinline__ void mma16816(float* d, uint32_t a0, uint32_t a1, uint32_t a2,
                                         uint32_t a3, uint32_t b0, uint32_t b1) {
    asm volatile(
        "mma.sync.aligned.m16n8k16.row.col.f32.f16.f16.f32 "
        "{%0,%1,%2,%3}, {%4,%5,%6,%7}, {%8,%9}, {%0,%1,%2,%3};"
        : "+f"(d[0]), "+f"(d[1]), "+f"(d[2]), "+f"(d[3])
        : "r"(a0), "r"(a1), "r"(a2), "r"(a3), "r"(b0), "r"(b1));
}
// fp16-accumulate (GEMM inner chains of 2 MMAs)
__device__ __forceinline__ void mma16816h(uint32_t* d, uint32_t a0, uint32_t a1, uint32_t a2,
                                          uint32_t a3, uint32_t b0, uint32_t b1) {
    asm volatile(
        "mma.sync.aligned.m16n8k16.row.col.f16.f16.f16.f16 "
        "{%0,%1}, {%2,%3,%4,%5}, {%6,%7}, {%0,%1};"
        : "+r"(d[0]), "+r"(d[1])
        : "r"(a0), "r"(a1), "r"(a2), "r"(a3), "r"(b0), "r"(b1));
}
__device__ __forceinline__ void cp_async16(uint32_t saddr, const void* gaddr) {
    asm volatile("cp.async.cg.shared.global [%0], [%1], 16;" :: "r"(saddr), "l"(gaddr) : "memory");
}

// ---------------------------------------------------------------------------
// prep kernels
// ---------------------------------------------------------------------------
__global__ void prep_x_kernel(const float* __restrict__ X, __half* __restrict__ Y) {
    size_t idx = (size_t)blockIdx.x * 256 + threadIdx.x;
    float4 f = *(const float4*)(X + idx * 4);
    uint32_t h0 = pack2_f16(f.x, f.y), h1 = pack2_f16(f.z, f.w);
    *(uint2*)(Y + idx * 4) = make_uint2(h0, h1);
}

__global__ void prep_w_kernel(const float* __restrict__ W,
                              __half* __restrict__ hi, int K, int N) {
    int idx = blockIdx.x * 256 + threadIdx.x;
    if (idx >= K * N) return;
    int k = idx / N, n = idx % N;
    hi[(size_t)n * K + k] = __float2half_rn(W[idx]);
}

__global__ void prep_bm_kernel(const float* __restrict__ mask,
                               const float* __restrict__ bias_table,
                               const int* __restrict__ rel_index,
                               float* __restrict__ bm) {
    int idx = blockIdx.x * 256 + threadIdx.x;
    if (idx >= NWIN * HEADS * WIN * WIN) return;
    int rc = idx % (WIN * WIN);
    int nwh = idx / (WIN * WIN);
    int h = nwh % HEADS, nw = nwh / HEADS;
    bm[idx] = mask[nw * WIN * WIN + rc] + bias_table[rel_index[rc] * HEADS + h];
}

// ---------------------------------------------------------------------------
// Tile geometry (GEMMs)
// ---------------------------------------------------------------------------
#define BM 128
#define BN 128
#define KC 64
#define NCHUNK (KTOT / KC)
#define PITCHB 144
#define TILEB (128 * PITCHB)

#define GM_STAGE (2 * TILEB)
#define GM_SMEM (2 * GM_STAGE)

#define GM_ISSUE(stg, k0, Abase, Bhi, bn)                                        \
    do {                                                                         \
        _Pragma("unroll")                                                        \
        for (int i = 0; i < 8; i++) {                                            \
            int g = tid + 256 * i;                                               \
            int sel = g >> 10;                                                   \
            int r = g & 1023;                                                    \
            int row = r >> 3, k8 = r & 7;                                        \
            const __half* src = (sel ? (Bhi) + (size_t)((bn) + row) * KTOT       \
                                     : (Abase) + (size_t)row * KTOT) + (k0) + k8 * 8; \
            cp_async16((stg) + sel * TILEB + row * PITCHB + k8 * 16, src);       \
        }                                                                        \
        asm volatile("cp.async.commit_group;" ::: "memory");                     \
    } while (0)

// R11 loop structure; f16-acc chains of 2 MMAs promoted into fp32 master acc.
// Full 16-tile body, B-frags loaded once per kk. Requires occupancy 1 (regs).
#define GM_MAINLOOP(Abase, Bhi, bn)                                              \
    GM_ISSUE(sb, 0, Abase, Bhi, bn);                                             \
    for (int c = 0; c < NCHUNK; c++) {                                           \
        const uint32_t sp = sb + (uint32_t)(c & 1) * GM_STAGE;                   \
        const bool pf = (c + 1 < NCHUNK);                                        \
        if (pf) GM_ISSUE(sb + (uint32_t)((c + 1) & 1) * GM_STAGE, (c + 1) * KC, Abase, Bhi, bn); \
        if (pf) { asm volatile("cp.async.wait_group 1;" ::: "memory"); }         \
        else    { asm volatile("cp.async.wait_group 0;" ::: "memory"); }         \
        __syncthreads();                                                         \
        uint32_t cacc[4][4][2];                                                  \
        _Pragma("unroll")                                                        \
        for (int mt = 0; mt < 4; mt++)                                           \
            _Pragma("unroll")                                                    \
            for (int nt = 0; nt < 4; nt++) { cacc[mt][nt][0] = 0u; cacc[mt][nt][1] = 0u; } \
        _Pragma("unroll")                                                        \
        for (int kk = 0; kk < 4; kk++) {                                         \
            const uint32_t kbyte = kk * 32;                                      \
            uint32_t Ar[4][4], Bh[2][4];                                         \
            _Pragma("unroll")                                                    \
            for (int mt = 0; mt < 4; mt++)                                       \
                ldmx4(Ar[mt][0], Ar[mt][1], Ar[mt][2], Ar[mt][3],                \
                      sp + (wm * 64 + mt * 16 + a_r) * PITCHB + kbyte + a_c);    \
            _Pragma("unroll")                                                    \
            for (int p = 0; p < 2; p++)                                          \
                ldmx4(Bh[p][0], Bh[p][1], Bh[p][2], Bh[p][3],                    \
                      sp + TILEB + (wn * 32 + p * 16 + b_noff) * PITCHB + kbyte + b_koff); \
            _Pragma("unroll")                                                    \
            for (int mt = 0; mt < 4; mt++)                                       \
                _Pragma("unroll")                                                \
                for (int nt = 0; nt < 4; nt++) {                                 \
                    const int p = nt >> 1, hh = (nt & 1) * 2;                    \
                    mma16816h(cacc[mt][nt], Ar[mt][0], Ar[mt][1], Ar[mt][2], Ar[mt][3], \
                              Bh[p][hh], Bh[p][hh + 1]);                         \
                }                                                                \
            if (kk & 1) {                                                        \
                _Pragma("unroll")                                                \
                for (int mt = 0; mt < 4; mt++)                                   \
                    _Pragma("unroll")                                            \
                    for (int nt = 0; nt < 4; nt++) {                             \
                        float2 lo = __half22float2(*(__half2*)&cacc[mt][nt][0]); \
                        float2 hi = __half22float2(*(__half2*)&cacc[mt][nt][1]); \
                        acc[mt][nt][0] += lo.x;                                  \
                        acc[mt][nt][1] += lo.y;                                  \
                        acc[mt][nt][2] += hi.x;                                  \
                        acc[mt][nt][3] += hi.y;                                  \
                        cacc[mt][nt][0] = 0u; cacc[mt][nt][1] = 0u;              \
                    }                                                            \
            }                                                                    \
        }                                                                        \
        __syncthreads();                                                         \
    }

// ---------------------------------------------------------------------------
// qkv GEMM: 1-term fp16, chunk-promoted f16 acc; C fp16 (q scaled)
// ---------------------------------------------------------------------------
__global__ __launch_bounds__(256, 1)
void qkv_gemm_kernel(const __half* __restrict__ A,
                     const __half* __restrict__ Bhi,
                     const float* __restrict__ bias, __half* __restrict__ C) {
    extern __shared__ char smem[];
    const uint32_t sb = smem_u32(smem);
    const int tid = threadIdx.x;
    const int warp = tid >> 5, lane = tid & 31;
    const int wm = warp >> 2, wn = warp & 3;
    const int bm = blockIdx.y * BM, bn = blockIdx.x * BN;

    float acc[4][4][4];
#pragma unroll
    for (int i = 0; i < 4; i++)
#pragma unroll
        for (int j = 0; j < 4; j++)
#pragma unroll
            for (int r = 0; r < 4; r++) acc[i][j][r] = 0.f;

    const __half* Abase = A + (size_t)bm * KTOT;
    const int a_r = lane & 15;
    const int a_c = (lane >> 4) * 16;
    const int b_lrow = lane & 7;
    const int b_q = lane >> 3;
    const int b_noff = ((b_q >> 1) * 8) + b_lrow;
    const int b_koff = (b_q & 1) * 16;

    GM_MAINLOOP(Abase, Bhi, bn)

    const int gid = lane >> 2, tig = lane & 3;
    const float qscale = 0.17677669529663687f;
#pragma unroll
    for (int mt = 0; mt < 4; mt++) {
        const int row = bm + wm * 64 + mt * 16 + gid;
#pragma unroll
        for (int nt = 0; nt < 4; nt++) {
            const int col = bn + wn * 32 + nt * 8 + tig * 2;
            const float b0 = bias[col], b1 = bias[col + 1];
            const float s = (col < DIMC) ? qscale : 1.0f;
            __half2 v0 = __floats2half2_rn((acc[mt][nt][0] + b0) * s, (acc[mt][nt][1] + b1) * s);
            __half2 v1 = __floats2half2_rn((acc[mt][nt][2] + b0) * s, (acc[mt][nt][3] + b1) * s);
            *(__half2*)(C + (size_t)row * QKVC + col) = v0;
            *(__half2*)(C + (size_t)(row + 8) * QKVC + col) = v1;
        }
    }
}

// ---------------------------------------------------------------------------
// proj GEMM: 1-term fp16, chunk-promoted f16 acc; C fp32
// ---------------------------------------------------------------------------
__global__ __launch_bounds__(256, 1)
void proj_gemm_kernel(const __half* __restrict__ A,
                      const __half* __restrict__ Bhi,
                      const float* __restrict__ bias, float* __restrict__ C) {
    extern __shared__ char smem[];
    const uint32_t sb = smem_u32(smem);
    const int tid = threadIdx.x;
    const int warp = tid >> 5, lane = tid & 31;
    const int wm = warp >> 2, wn = warp & 3;
    const int bm = blockIdx.y * BM, bn = blockIdx.x * BN;

    float acc[4][4][4];
#pragma unroll
    for (int i = 0; i < 4; i++)
#pragma unroll
        for (int j = 0; j < 4; j++)
#pragma unroll
            for (int r = 0; r < 4; r++) acc[i][j][r] = 0.f;

    const __half* Abase = A + (size_t)bm * KTOT;
    const int a_r = lane & 15;
    const int a_c = (lane >> 4) * 16;
    const int b_lrow = lane & 7;
    const int b_q = lane >> 3;
    const int b_noff = ((b_q >> 1) * 8) + b_lrow;
    const int b_koff = (b_q & 1) * 16;

    GM_MAINLOOP(Abase, Bhi, bn)

    const int gid = lane >> 2, tig = lane & 3;
#pragma unroll
    for (int mt = 0; mt < 4; mt++) {
        const int row = bm + wm * 64 + mt * 16 + gid;
#pragma unroll
        for (int nt = 0; nt < 4; nt++) {
            const int col = bn + wn * 32 + nt * 8 + tig * 2;
            const float b0 = bias[col], b1 = bias[col + 1];
            float2 v0 = make_float2(acc[mt][nt][0] + b0, acc[mt][nt][1] + b1);
            float2 v1 = make_float2(acc[mt][nt][2] + b0, acc[mt][nt][3] + b1);
            *(float2*)(C + (size_t)row * DIMC + col) = v0;
            *(float2*)(C + (size_t)(row + 8) * DIMC + col) = v1;
        }
    }
}

// ---------------------------------------------------------------------------
// Tensor-core attention, amortized (unchanged, fp32 accumulate)
// ---------------------------------------------------------------------------
#define AQ_PITCH 80
#define ATN_TEN (64 * AQ_PITCH)
#define ATN_STAGE (3 * ATN_TEN)
#define BI_PITCH 66
#define GRP 8

__global__ __launch_bounds__(128)
void attn_mma_kernel(const __half* __restrict__ qkv,
                     const float* __restrict__ bm,
                     __half* __restrict__ out) {
    __shared__ __align__(16) char sm[2 * ATN_STAGE + 64 * BI_PITCH * 4];
    const uint32_t sb = smem_u32(sm);
    const uint32_t sBI = sb + 2 * ATN_STAGE;

    const int nw = blockIdx.x, h = blockIdx.y;
    const int tid = threadIdx.x;
    const int warp = tid >> 5, lane = tid & 31;
    const int gid = lane >> 2, tig = lane & 3;
    const int row0 = 16 * warp + gid;

    const float* bmrow = bm + (size_t)(nw * HEADS + h) * (WIN * WIN);
    for (int idx = tid; idx < 64 * 64; idx += 128) {
        int r = idx >> 6, c = idx & 63;
        float v = 0.f;
        if (r < WIN) v = (c < WIN) ? bmrow[r * WIN + c] : -1e30f;
        asm volatile("st.shared.b32 [%0], %1;"
                     :: "r"(sBI + (uint32_t)(r * BI_PITCH + c) * 4), "f"(v) : "memory");
    }
    for (int idx = tid; idx < 450; idx += 128) {
        int st = idx / 225, rem = idx % 225;
        int t = rem / 75, r2 = rem % 75;
        int row = 49 + r2 / 5, ch = r2 % 5;
        asm volatile("st.shared.v4.b32 [%0], {%1,%1,%1,%1};"
                     :: "r"(sb + st * ATN_STAGE + t * ATN_TEN + row * AQ_PITCH + ch * 16),
                        "r"(0) : "memory");
    }
    __syncthreads();

    float Sb[8][4];
#pragma unroll
    for (int nt = 0; nt < 8; nt++) {
        const uint32_t col4 = (uint32_t)(8 * nt + 2 * tig) * 4;
        asm volatile("ld.shared.v2.f32 {%0,%1}, [%2];" : "=f"(Sb[nt][0]), "=f"(Sb[nt][1])
                     : "r"(sBI + (uint32_t)row0 * BI_PITCH * 4 + col4));
        asm volatile("ld.shared.v2.f32 {%0,%1}, [%2];" : "=f"(Sb[nt][2]), "=f"(Sb[nt][3])
                     : "r"(sBI + (uint32_t)(row0 + 8) * BI_PITCH * 4 + col4));
    }

    const int a_r = lane & 15;
    const int a_c = (lane >> 4) * 16;
    const int b_lrow = lane & 7;
    const int b_q = lane >> 3;
    const int b_noff = (b_q >> 1) * 8 + b_lrow;
    const int b_koff = (b_q & 1) * 16;
    const uint32_t v_row = (uint32_t)((lane & 7) + 8 * ((lane >> 3) & 1));
    const uint32_t v_cb  = (uint32_t)((lane >> 4) * 16);

    const int img0 = blockIdx.z * GRP;

#define AT_ISSUE(stg, ii)                                                         \
    do {                                                                          \
        const __half* base_ = qkv + ((size_t)((img0 + (ii)) * NWIN + nw) * WIN) * QKVC + h * HD; \
        _Pragma("unroll")                                                         \
        for (int u = 0; u < 5; u++) {                                             \
            int idx = tid + 128 * u;                                              \
            if (idx < 588) {                                                      \
                int i = idx / 12, rem = idx % 12;                                 \
                int sel = rem >> 2, ch = rem & 3;                                 \
                cp_async16((stg) + sel * ATN_TEN + i * AQ_PITCH + ch * 16,        \
                           base_ + (size_t)i * QKVC + sel * DIMC + ch * 8);       \
            }                                                                     \
        }                                                                         \
        asm volatile("cp.async.commit_group;" ::: "memory");                      \
    } while (0)

    AT_ISSUE(sb, 0);

    for (int ii = 0; ii < GRP; ii++) {
        const uint32_t sp = sb + (uint32_t)(ii & 1) * ATN_STAGE;
        const uint32_t sQ = sp, sK = sp + ATN_TEN, sV = sp + 2 * ATN_TEN;
        const bool pf = (ii + 1 < GRP);
        if (pf) AT_ISSUE(sb + (uint32_t)((ii + 1) & 1) * ATN_STAGE, ii + 1);
        if (pf) { asm volatile("cp.async.wait_group 1;" ::: "memory"); }
        else    { asm volatile("cp.async.wait_group 0;" ::: "memory"); }
        __syncthreads();

        uint32_t Aq[2][4];
#pragma unroll
        for (int t = 0; t < 2; t++)
            ldmx4(Aq[t][0], Aq[t][1], Aq[t][2], Aq[t][3],
                  sQ + (16 * warp + a_r) * AQ_PITCH + t * 32 + a_c);

        float S[8][4];
#pragma unroll
        for (int nt = 0; nt < 8; nt++)
#pragma unroll
            for (int r = 0; r < 4; r++) S[nt][r] = Sb[nt][r];

#pragma unroll
        for (int p = 0; p < 4; p++)
#pragma unroll
            for (int t = 0; t < 2; t++) {
                uint32_t Bk[4];
                ldmx4(Bk[0], Bk[1], Bk[2], Bk[3],
                      sK + (16 * p + b_noff) * AQ_PITCH + t * 32 + b_koff);
                mma16816(S[2 * p],     Aq[t][0], Aq[t][1], Aq[t][2], Aq[t][3], Bk[0], Bk[1]);
                mma16816(S[2 * p + 1], Aq[t][0], Aq[t][1], Aq[t][2], Aq[t][3], Bk[2], Bk[3]);
            }

        float m0 = -3.0e38f, m1 = -3.0e38f;
#pragma unroll
        for (int nt = 0; nt < 8; nt++) {
            m0 = fmaxf(m0, fmaxf(S[nt][0], S[nt][1]));
            m1 = fmaxf(m1, fmaxf(S[nt][2], S[nt][3]));
        }
        m0 = fmaxf(m0, __shfl_xor_sync(0xffffffffu, m0, 1));
        m0 = fmaxf(m0, __shfl_xor_sync(0xffffffffu, m0, 2));
        m1 = fmaxf(m1, __shfl_xor_sync(0xffffffffu, m1, 1));
        m1 = fmaxf(m1, __shfl_xor_sync(0xffffffffu, m1, 2));

        float s0 = 0.f, s1 = 0.f;
#pragma unroll
        for (int nt = 0; nt < 8; nt++) {
            S[nt][0] = __expf(S[nt][0] - m0);
            S[nt][1] = __expf(S[nt][1] - m0);
            S[nt][2] = __expf(S[nt][2] - m1);
            S[nt][3] = __expf(S[nt][3] - m1);
            s0 += S[nt][0] + S[nt][1];
            s1 += S[nt][2] + S[nt][3];
        }
        s0 += __shfl_xor_sync(0xffffffffu, s0, 1);
        s0 += __shfl_xor_sync(0xffffffffu, s0, 2);
        s1 += __shfl_xor_sync(0xffffffffu, s1, 1);
        s1 += __shfl_xor_sync(0xffffffffu, s1, 2);
        const float inv0 = 1.0f / s0, inv1 = 1.0f / s1;

        uint32_t P[4][4];
#pragma unroll
        for (int t = 0; t < 4; t++) {
            P[t][0] = pack2_f16(S[2 * t][0], S[2 * t][1]);
            P[t][1] = pack2_f16(S[2 * t][2], S[2 * t][3]);
            P[t][2] = pack2_f16(S[2 * t + 1][0], S[2 * t + 1][1]);
            P[t][3] = pack2_f16(S[2 * t + 1][2], S[2 * t + 1][3]);
        }

        float O[4][4];
#pragma unroll
        for (int i = 0; i < 4; i++)
#pragma unroll
            for (int r = 0; r < 4; r++) O[i][r] = 0.f;

#pragma unroll
        for (int t = 0; t < 4; t++)
#pragma unroll
            for (int g = 0; g < 2; g++) {
                uint32_t Bv[4];
                ldmx4t(Bv[0], Bv[1], Bv[2], Bv[3],
                       sV + (16 * t + v_row) * AQ_PITCH + 32 * g + v_cb);
                mma16816(O[2 * g],     P[t][0], P[t][1], P[t][2], P[t][3], Bv[0], Bv[1]);
                mma16816(O[2 * g + 1], P[t][0], P[t][1], P[t][2], P[t][3], Bv[2], Bv[3]);
            }

        const size_t ob = (size_t)((img0 + ii) * NWIN + nw) * WIN;
#pragma unroll
        for (int nt = 0; nt < 4; nt++) {
            const int col = h * HD + 8 * nt + 2 * tig;
            if (row0 < WIN) {
                __half2 v = __floats2half2_rn(O[nt][0] * inv0, O[nt][1] * inv0);
                *(__half2*)(out + (ob + row0) * DIMC + col) = v;
            }
            if (row0 + 8 < WIN) {
                __half2 v = __floats2half2_rn(O[nt][2] * inv1, O[nt][3] * inv1);
                *(__half2*)(out + (ob + row0 + 8) * DIMC + col) = v;
            }
        }
        __syncthreads();
    }
#undef AT_ISSUE
}

// ---------------------------------------------------------------------------
extern "C" void kernel_launch(void* const* d_in, const int* in_sizes, int n_in,
                              void* d_out, int out_size) {
    const float* x          = (const float*)d_in[0];
    const float* mask       = (const float*)d_in[1];
    const float* qkv_w      = (const float*)d_in[2];
    const float* qkv_b      = (const float*)d_in[3];
    const float* proj_w     = (const float*)d_in[4];
    const float* proj_b     = (const float*)d_in[5];
    const float* bias_table = (const float*)d_in[6];
    const int*   rel_index  = (const int*)d_in[7];
    float* out = (float*)d_out;

    __half *x16, *qkv, *att, *wq_hi, *wp_hi;
    float* bmc;
    cudaGetSymbolAddress((void**)&x16, g_x16);
    cudaGetSymbolAddress((void**)&qkv, g_qkv);
    cudaGetSymbolAddress((void**)&att, g_att);
    cudaGetSymbolAddress((void**)&wq_hi, g_wqkv_hi);
    cudaGetSymbolAddress((void**)&wp_hi, g_wprj_hi);
    cudaGetSymbolAddress((void**)&bmc, g_bm);

    cudaFuncSetAttribute(qkv_gemm_kernel, cudaFuncAttributeMaxDynamicSharedMemorySize, GM_SMEM);
    cudaFuncSetAttribute(proj_gemm_kernel, cudaFuncAttributeMaxDynamicSharedMemorySize, GM_SMEM);

    // 0) preps
    prep_x_kernel<<<(size_t)MROWS * KTOT / 4 / 256, 256>>>(x, x16);
    prep_w_kernel<<<(KTOT * QKVC + 255) / 256, 256>>>(qkv_w, wq_hi, KTOT, QKVC);
    prep_w_kernel<<<(KTOT * DIMC + 255) / 256, 256>>>(proj_w, wp_hi, KTOT, DIMC);
    prep_bm_kernel<<<(NWIN * HEADS * WIN * WIN + 255) / 256, 256>>>(mask, bias_table,
                                                                    rel_index, bmc);
    // 1) qkv GEMM (1-term, chunk-promoted f16 acc, occ 1)
    {
        dim3 grid(QKVC / BN, MROWS / BM);
        qkv_gemm_kernel<<<grid, 256, GM_SMEM>>>(x16, wq_hi, qkv_b, qkv);
    }
    // 2) tensor-core attention
    {
        dim3 grid(NWIN, HEADS, BATCH / NWIN / GRP);
        attn_mma_kernel<<<grid, 128>>>(qkv, bmc, att);
    }
    // 3) proj GEMM (1-term, chunk-promoted f16 acc, occ 1)
    {
        dim3 grid(DIMC / BN, MROWS / BM);
        proj_gemm_kernel<<<grid, 256, GM_SMEM>>>(att, wp_hi, proj_b, out);
    }
}

// round 15
// speedup vs baseline: 1.4871x; 1.4115x over previous
#include <cuda_runtime.h>
#include <cuda_fp16.h>
#include <cstdint>

#define WIN 49
#define HEADS 12
#define HD 32
#define DIMC 384
#define BATCH 4096
#define NWIN 64
#define QKVC (3 * DIMC)     // 1152
#define MROWS (BATCH * WIN) // 200704
#define KTOT 384

// ---------------- scratch (allocation-free rule: __device__ globals) -------
__device__ __half g_x16[(size_t)MROWS * KTOT];
__device__ __half g_qkv[(size_t)MROWS * QKVC];
__device__ __half g_att[(size_t)MROWS * DIMC];
__device__ __half g_wqkv_hi[QKVC * KTOT];
__device__ __half g_wprj_hi[DIMC * KTOT];
__device__ float  g_bm[(size_t)NWIN * HEADS * WIN * WIN]; // mask+bias combined

// ---------------- helpers ---------------------------------------------------
__device__ __forceinline__ uint32_t smem_u32(const void* p) {
    uint32_t a;
    asm("{ .reg .u64 t; cvta.to.shared.u64 t, %1; cvt.u32.u64 %0, t; }" : "=r"(a) : "l"(p));
    return a;
}
__device__ __forceinline__ uint32_t pack2_f16(float even, float odd) {
    uint32_t r;
    asm("cvt.rn.f16x2.f32 %0, %1, %2;" : "=r"(r) : "f"(odd), "f"(even));
    return r;
}
__device__ __forceinline__ void ldmx4(uint32_t& r0, uint32_t& r1, uint32_t& r2, uint32_t& r3,
                                      uint32_t addr) {
    asm volatile("ldmatrix.sync.aligned.m8n8.x4.shared.b16 {%0,%1,%2,%3}, [%4];"
                 : "=r"(r0), "=r"(r1), "=r"(r2), "=r"(r3) : "r"(addr));
}
__device__ __forceinline__ void ldmx4t(uint32_t& r0, uint32_t& r1, uint32_t& r2, uint32_t& r3,
                                       uint32_t addr) {
    asm volatile("ldmatrix.sync.aligned.m8n8.x4.trans.shared.b16 {%0,%1,%2,%3}, [%4];"
                 : "=r"(r0), "=r"(r1), "=r"(r2), "=r"(r3) : "r"(addr));
}
// fp32-accumulate mma (all compute)
__device__ __forceinline__ void mma16816(float* d, uint32_t a0, uint32_t a1, uint32_t a2,
                                         uint32_t a3, uint32_t b0, uint32_t b1) {
    asm volatile(
        "mma.sync.aligned.m16n8k16.row.col.f32.f16.f16.f32 "
        "{%0,%1,%2,%3}, {%4,%5,%6,%7}, {%8,%9}, {%0,%1,%2,%3};"
        : "+f"(d[0]), "+f"(d[1]), "+f"(d[2]), "+f"(d[3])
        : "r"(a0), "r"(a1), "r"(a2), "r"(a3), "r"(b0), "r"(b1));
}
__device__ __forceinline__ void cp_async16(uint32_t saddr, const void* gaddr) {
    asm volatile("cp.async.cg.shared.global [%0], [%1], 16;" :: "r"(saddr), "l"(gaddr) : "memory");
}

// ---------------------------------------------------------------------------
// Merged prep kernel: block ranges dispatch the 4 independent prep tasks.
// ---------------------------------------------------------------------------
#define PX_BLOCKS ((MROWS * KTOT / 4) / 256)                      // 75264
#define WQ_BLOCKS ((KTOT * QKVC + 255) / 256)                     // 1728
#define WP_BLOCKS ((KTOT * DIMC + 255) / 256)                     // 576
#define BMK_BLOCKS ((NWIN * HEADS * WIN * WIN + 255) / 256)       // 7203
#define PREP_BLOCKS (PX_BLOCKS + WQ_BLOCKS + WP_BLOCKS + BMK_BLOCKS)

__global__ void prep_all_kernel(const float* __restrict__ X, __half* __restrict__ X16,
                                const float* __restrict__ Wq, __half* __restrict__ WqH,
                                const float* __restrict__ Wp, __half* __restrict__ WpH,
                                const float* __restrict__ mask,
                                const float* __restrict__ bias_table,
                                const int* __restrict__ rel_index,
                                float* __restrict__ bm) {
    int blk = blockIdx.x;
    if (blk < PX_BLOCKS) {
        size_t idx = (size_t)blk * 256 + threadIdx.x;
        float4 f = *(const float4*)(X + idx * 4);
        uint32_t h0 = pack2_f16(f.x, f.y), h1 = pack2_f16(f.z, f.w);
        *(uint2*)(X16 + idx * 4) = make_uint2(h0, h1);
        return;
    }
    blk -= PX_BLOCKS;
    if (blk < WQ_BLOCKS) {
        int idx = blk * 256 + threadIdx.x;
        if (idx < KTOT * QKVC) {
            int k = idx / QKVC, n = idx % QKVC;
            WqH[(size_t)n * KTOT + k] = __float2half_rn(Wq[idx]);
        }
        return;
    }
    blk -= WQ_BLOCKS;
    if (blk < WP_BLOCKS) {
        int idx = blk * 256 + threadIdx.x;
        if (idx < KTOT * DIMC) {
            int k = idx / DIMC, n = idx % DIMC;
            WpH[(size_t)n * KTOT + k] = __float2half_rn(Wp[idx]);
        }
        return;
    }
    blk -= WP_BLOCKS;
    {
        int idx = blk * 256 + threadIdx.x;
        if (idx < NWIN * HEADS * WIN * WIN) {
            int rc = idx % (WIN * WIN);
            int nwh = idx / (WIN * WIN);
            int h = nwh % HEADS, nw = nwh / HEADS;
            bm[idx] = mask[nw * WIN * WIN + rc] + bias_table[rel_index[rc] * HEADS + h];
        }
    }
}

// ---------------------------------------------------------------------------
// Tile geometry (GEMMs)
// ---------------------------------------------------------------------------
#define BM 128
#define BN 128
#define KC 64
#define NCHUNK (KTOT / KC)
#define PITCHB 144
#define TILEB (128 * PITCHB)

#define GM_STAGE (2 * TILEB)
#define GM_SMEM (2 * GM_STAGE)

#define GM_ISSUE(stg, k0, Abase, Bhi, bn)                                        \
    do {                                                                         \
        _Pragma("unroll")                                                        \
        for (int i = 0; i < 8; i++) {                                            \
            int g = tid + 256 * i;                                               \
            int sel = g >> 10;                                                   \
            int r = g & 1023;                                                    \
            int row = r >> 3, k8 = r & 7;                                        \
            const __half* src = (sel ? (Bhi) + (size_t)((bn) + row) * KTOT       \
                                     : (Abase) + (size_t)row * KTOT) + (k0) + k8 * 8; \
            cp_async16((stg) + sel * TILEB + row * PITCHB + k8 * 16, src);       \
        }                                                                        \
        asm volatile("cp.async.commit_group;" ::: "memory");                     \
    } while (0)

// R11 mainloop: f32-acc MMA, double-buffered cp.async
#define GM_MAINLOOP(Abase, Bhi, bn)                                              \
    GM_ISSUE(sb, 0, Abase, Bhi, bn);                                             \
    for (int c = 0; c < NCHUNK; c++) {                                           \
        const uint32_t sp = sb + (uint32_t)(c & 1) * GM_STAGE;                   \
        const bool pf = (c + 1 < NCHUNK);                                        \
        if (pf) GM_ISSUE(sb + (uint32_t)((c + 1) & 1) * GM_STAGE, (c + 1) * KC, Abase, Bhi, bn); \
        if (pf) { asm volatile("cp.async.wait_group 1;" ::: "memory"); }         \
        else    { asm volatile("cp.async.wait_group 0;" ::: "memory"); }         \
        __syncthreads();                                                         \
        _Pragma("unroll")                                                        \
        for (int kk = 0; kk < 4; kk++) {                                         \
            const uint32_t kbyte = kk * 32;                                      \
            uint32_t Ar[4][4], Bh[2][4];                                         \
            _Pragma("unroll")                                                    \
            for (int mt = 0; mt < 4; mt++)                                       \
                ldmx4(Ar[mt][0], Ar[mt][1], Ar[mt][2], Ar[mt][3],                \
                      sp + (wm * 64 + mt * 16 + a_r) * PITCHB + kbyte + a_c);    \
            _Pragma("unroll")                                                    \
            for (int p = 0; p < 2; p++)                                          \
                ldmx4(Bh[p][0], Bh[p][1], Bh[p][2], Bh[p][3],                    \
                      sp + TILEB + (wn * 32 + p * 16 + b_noff) * PITCHB + kbyte + b_koff); \
            _Pragma("unroll")                                                    \
            for (int mt = 0; mt < 4; mt++)                                       \
                _Pragma("unroll")                                                \
                for (int nt = 0; nt < 4; nt++) {                                 \
                    const int p = nt >> 1, hh = (nt & 1) * 2;                    \
                    mma16816(acc[mt][nt], Ar[mt][0], Ar[mt][1], Ar[mt][2], Ar[mt][3], \
                             Bh[p][hh], Bh[p][hh + 1]);                          \
                }                                                                \
        }                                                                        \
        __syncthreads();                                                         \
    }

// ---------------------------------------------------------------------------
// qkv GEMM: 1-term fp16, f32 acc; C fp16 (q scaled)
// ---------------------------------------------------------------------------
__global__ __launch_bounds__(256, 2)
void qkv_gemm_kernel(const __half* __restrict__ A,
                     const __half* __restrict__ Bhi,
                     const float* __restrict__ bias, __half* __restrict__ C) {
    extern __shared__ char smem[];
    const uint32_t sb = smem_u32(smem);
    const int tid = threadIdx.x;
    const int warp = tid >> 5, lane = tid & 31;
    const int wm = warp >> 2, wn = warp & 3;
    const int bm = blockIdx.y * BM, bn = blockIdx.x * BN;

    float acc[4][4][4];
#pragma unroll
    for (int i = 0; i < 4; i++)
#pragma unroll
        for (int j = 0; j < 4; j++)
#pragma unroll
            for (int r = 0; r < 4; r++) acc[i][j][r] = 0.f;

    const __half* Abase = A + (size_t)bm * KTOT;
    const int a_r = lane & 15;
    const int a_c = (lane >> 4) * 16;
    const int b_lrow = lane & 7;
    const int b_q = lane >> 3;
    const int b_noff = ((b_q >> 1) * 8) + b_lrow;
    const int b_koff = (b_q & 1) * 16;

    GM_MAINLOOP(Abase, Bhi, bn)

    const int gid = lane >> 2, tig = lane & 3;
    const float qscale = 0.17677669529663687f;
#pragma unroll
    for (int mt = 0; mt < 4; mt++) {
        const int row = bm + wm * 64 + mt * 16 + gid;
#pragma unroll
        for (int nt = 0; nt < 4; nt++) {
            const int col = bn + wn * 32 + nt * 8 + tig * 2;
            const float b0 = bias[col], b1 = bias[col + 1];
            const float s = (col < DIMC) ? qscale : 1.0f;
            __half2 v0 = __floats2half2_rn((acc[mt][nt][0] + b0) * s, (acc[mt][nt][1] + b1) * s);
            __half2 v1 = __floats2half2_rn((acc[mt][nt][2] + b0) * s, (acc[mt][nt][3] + b1) * s);
            *(__half2*)(C + (size_t)row * QKVC + col) = v0;
            *(__half2*)(C + (size_t)(row + 8) * QKVC + col) = v1;
        }
    }
}

// ---------------------------------------------------------------------------
// proj GEMM: 1-term fp16, f32 acc; C fp32
// ---------------------------------------------------------------------------
__global__ __launch_bounds__(256, 2)
void proj_gemm_kernel(const __half* __restrict__ A,
                      const __half* __restrict__ Bhi,
                      const float* __restrict__ bias, float* __restrict__ C) {
    extern __shared__ char smem[];
    const uint32_t sb = smem_u32(smem);
    const int tid = threadIdx.x;
    const int warp = tid >> 5, lane = tid & 31;
    const int wm = warp >> 2, wn = warp & 3;
    const int bm = blockIdx.y * BM, bn = blockIdx.x * BN;

    float acc[4][4][4];
#pragma unroll
    for (int i = 0; i < 4; i++)
#pragma unroll
        for (int j = 0; j < 4; j++)
#pragma unroll
            for (int r = 0; r < 4; r++) acc[i][j][r] = 0.f;

    const __half* Abase = A + (size_t)bm * KTOT;
    const int a_r = lane & 15;
    const int a_c = (lane >> 4) * 16;
    const int b_lrow = lane & 7;
    const int b_q = lane >> 3;
    const int b_noff = ((b_q >> 1) * 8) + b_lrow;
    const int b_koff = (b_q & 1) * 16;

    GM_MAINLOOP(Abase, Bhi, bn)

    const int gid = lane >> 2, tig = lane & 3;
#pragma unroll
    for (int mt = 0; mt < 4; mt++) {
        const int row = bm + wm * 64 + mt * 16 + gid;
#pragma unroll
        for (int nt = 0; nt < 4; nt++) {
            const int col = bn + wn * 32 + nt * 8 + tig * 2;
            const float b0 = bias[col], b1 = bias[col + 1];
            float2 v0 = make_float2(acc[mt][nt][0] + b0, acc[mt][nt][1] + b1);
            float2 v1 = make_float2(acc[mt][nt][2] + b0, acc[mt][nt][3] + b1);
            *(float2*)(C + (size_t)row * DIMC + col) = v0;
            *(float2*)(C + (size_t)(row + 8) * DIMC + col) = v1;
        }
    }
}

// ---------------------------------------------------------------------------
// Tensor-core attention, amortized; GRP=16 images per block
// ---------------------------------------------------------------------------
#define AQ_PITCH 80
#define ATN_TEN (64 * AQ_PITCH)
#define ATN_STAGE (3 * ATN_TEN)
#define BI_PITCH 66
#define GRP 16

__global__ __launch_bounds__(128)
void attn_mma_kernel(const __half* __restrict__ qkv,
                     const float* __restrict__ bm,
                     __half* __restrict__ out) {
    __shared__ __align__(16) char sm[2 * ATN_STAGE + 64 * BI_PITCH * 4];
    const uint32_t sb = smem_u32(sm);
    const uint32_t sBI = sb + 2 * ATN_STAGE;

    const int nw = blockIdx.x, h = blockIdx.y;
    const int tid = threadIdx.x;
    const int warp = tid >> 5, lane = tid & 31;
    const int gid = lane >> 2, tig = lane & 3;
    const int row0 = 16 * warp + gid;

    const float* bmrow = bm + (size_t)(nw * HEADS + h) * (WIN * WIN);
    for (int idx = tid; idx < 64 * 64; idx += 128) {
        int r = idx >> 6, c = idx & 63;
        float v = 0.f;
        if (r < WIN) v = (c < WIN) ? bmrow[r * WIN + c] : -1e30f;
        asm volatile("st.shared.b32 [%0], %1;"
                     :: "r"(sBI + (uint32_t)(r * BI_PITCH + c) * 4), "f"(v) : "memory");
    }
    for (int idx = tid; idx < 450; idx += 128) {
        int st = idx / 225, rem = idx % 225;
        int t = rem / 75, r2 = rem % 75;
        int row = 49 + r2 / 5, ch = r2 % 5;
        asm volatile("st.shared.v4.b32 [%0], {%1,%1,%1,%1};"
                     :: "r"(sb + st * ATN_STAGE + t * ATN_TEN + row * AQ_PITCH + ch * 16),
                        "r"(0) : "memory");
    }
    __syncthreads();

    float Sb[8][4];
#pragma unroll
    for (int nt = 0; nt < 8; nt++) {
        const uint32_t col4 = (uint32_t)(8 * nt + 2 * tig) * 4;
        asm volatile("ld.shared.v2.f32 {%0,%1}, [%2];" : "=f"(Sb[nt][0]), "=f"(Sb[nt][1])
                     : "r"(sBI + (uint32_t)row0 * BI_PITCH * 4 + col4));
        asm volatile("ld.shared.v2.f32 {%0,%1}, [%2];" : "=f"(Sb[nt][2]), "=f"(Sb[nt][3])
                     : "r"(sBI + (uint32_t)(row0 + 8) * BI_PITCH * 4 + col4));
    }

    const int a_r = lane & 15;
    const int a_c = (lane >> 4) * 16;
    const int b_lrow = lane & 7;
    const int b_q = lane >> 3;
    const int b_noff = (b_q >> 1) * 8 + b_lrow;
    const int b_koff = (b_q & 1) * 16;
    const uint32_t v_row = (uint32_t)((lane & 7) + 8 * ((lane >> 3) & 1));
    const uint32_t v_cb  = (uint32_t)((lane >> 4) * 16);

    const int img0 = blockIdx.z * GRP;

#define AT_ISSUE(stg, ii)                                                         \
    do {                                                                          \
        const __half* base_ = qkv + ((size_t)((img0 + (ii)) * NWIN + nw) * WIN) * QKVC + h * HD; \
        _Pragma("unroll")                                                         \
        for (int u = 0; u < 5; u++) {                                             \
            int idx = tid + 128 * u;                                              \
            if (idx < 588) {                                                      \
                int i = idx / 12, rem = idx % 12;                                 \
                int sel = rem >> 2, ch = rem & 3;                                 \
                cp_async16((stg) + sel * ATN_TEN + i * AQ_PITCH + ch * 16,        \
                           base_ + (size_t)i * QKVC + sel * DIMC + ch * 8);       \
            }                                                                     \
        }                                                                         \
        asm volatile("cp.async.commit_group;" ::: "memory");                      \
    } while (0)

    AT_ISSUE(sb, 0);

    for (int ii = 0; ii < GRP; ii++) {
        const uint32_t sp = sb + (uint32_t)(ii & 1) * ATN_STAGE;
        const uint32_t sQ = sp, sK = sp + ATN_TEN, sV = sp + 2 * ATN_TEN;
        const bool pf = (ii + 1 < GRP);
        if (pf) AT_ISSUE(sb + (uint32_t)((ii + 1) & 1) * ATN_STAGE, ii + 1);
        if (pf) { asm volatile("cp.async.wait_group 1;" ::: "memory"); }
        else    { asm volatile("cp.async.wait_group 0;" ::: "memory"); }
        __syncthreads();

        uint32_t Aq[2][4];
#pragma unroll
        for (int t = 0; t < 2; t++)
            ldmx4(Aq[t][0], Aq[t][1], Aq[t][2], Aq[t][3],
                  sQ + (16 * warp + a_r) * AQ_PITCH + t * 32 + a_c);

        float S[8][4];
#pragma unroll
        for (int nt = 0; nt < 8; nt++)
#pragma unroll
            for (int r = 0; r < 4; r++) S[nt][r] = Sb[nt][r];

#pragma unroll
        for (int p = 0; p < 4; p++)
#pragma unroll
            for (int t = 0; t < 2; t++) {
                uint32_t Bk[4];
                ldmx4(Bk[0], Bk[1], Bk[2], Bk[3],
                      sK + (16 * p + b_noff) * AQ_PITCH + t * 32 + b_koff);
                mma16816(S[2 * p],     Aq[t][0], Aq[t][1], Aq[t][2], Aq[t][3], Bk[0], Bk[1]);
                mma16816(S[2 * p + 1], Aq[t][0], Aq[t][1], Aq[t][2], Aq[t][3], Bk[2], Bk[3]);
            }

        float m0 = -3.0e38f, m1 = -3.0e38f;
#pragma unroll
        for (int nt = 0; nt < 8; nt++) {
            m0 = fmaxf(m0, fmaxf(S[nt][0], S[nt][1]));
            m1 = fmaxf(m1, fmaxf(S[nt][2], S[nt][3]));
        }
        m0 = fmaxf(m0, __shfl_xor_sync(0xffffffffu, m0, 1));
        m0 = fmaxf(m0, __shfl_xor_sync(0xffffffffu, m0, 2));
        m1 = fmaxf(m1, __shfl_xor_sync(0xffffffffu, m1, 1));
        m1 = fmaxf(m1, __shfl_xor_sync(0xffffffffu, m1, 2));

        float s0 = 0.f, s1 = 0.f;
#pragma unroll
        for (int nt = 0; nt < 8; nt++) {
            S[nt][0] = __expf(S[nt][0] - m0);
            S[nt][1] = __expf(S[nt][1] - m0);
            S[nt][2] = __expf(S[nt][2] - m1);
            S[nt][3] = __expf(S[nt][3] - m1);
            s0 += S[nt][0] + S[nt][1];
            s1 += S[nt][2] + S[nt][3];
        }
        s0 += __shfl_xor_sync(0xffffffffu, s0, 1);
        s0 += __shfl_xor_sync(0xffffffffu, s0, 2);
        s1 += __shfl_xor_sync(0xffffffffu, s1, 1);
        s1 += __shfl_xor_sync(0xffffffffu, s1, 2);
        const float inv0 = 1.0f / s0, inv1 = 1.0f / s1;

        uint32_t P[4][4];
#pragma unroll
        for (int t = 0; t < 4; t++) {
            P[t][0] = pack2_f16(S[2 * t][0], S[2 * t][1]);
            P[t][1] = pack2_f16(S[2 * t][2], S[2 * t][3]);
            P[t][2] = pack2_f16(S[2 * t + 1][0], S[2 * t + 1][1]);
            P[t][3] = pack2_f16(S[2 * t + 1][2], S[2 * t + 1][3]);
        }

        float O[4][4];
#pragma unroll
        for (int i = 0; i < 4; i++)
#pragma unroll
            for (int r = 0; r < 4; r++) O[i][r] = 0.f;

#pragma unroll
        for (int t = 0; t < 4; t++)
#pragma unroll
            for (int g = 0; g < 2; g++) {
                uint32_t Bv[4];
                ldmx4t(Bv[0], Bv[1], Bv[2], Bv[3],
                       sV + (16 * t + v_row) * AQ_PITCH + 32 * g + v_cb);
                mma16816(O[2 * g],     P[t][0], P[t][1], P[t][2], P[t][3], Bv[0], Bv[1]);
                mma16816(O[2 * g + 1], P[t][0], P[t][1], P[t][2], P[t][3], Bv[2], Bv[3]);
            }

        const size_t ob = (size_t)((img0 + ii) * NWIN + nw) * WIN;
#pragma unroll
        for (int nt = 0; nt < 4; nt++) {
            const int col = h * HD + 8 * nt + 2 * tig;
            if (row0 < WIN) {
                __half2 v = __floats2half2_rn(O[nt][0] * inv0, O[nt][1] * inv0);
                *(__half2*)(out + (ob + row0) * DIMC + col) = v;
            }
            if (row0 + 8 < WIN) {
                __half2 v = __floats2half2_rn(O[nt][2] * inv1, O[nt][3] * inv1);
                *(__half2*)(out + (ob + row0 + 8) * DIMC + col) = v;
            }
        }
        __syncthreads();
    }
#undef AT_ISSUE
}

// ---------------------------------------------------------------------------
extern "C" void kernel_launch(void* const* d_in, const int* in_sizes, int n_in,
                              void* d_out, int out_size) {
    const float* x          = (const float*)d_in[0];
    const float* mask       = (const float*)d_in[1];
    const float* qkv_w      = (const float*)d_in[2];
    const float* qkv_b      = (const float*)d_in[3];
    const float* proj_w     = (const float*)d_in[4];
    const float* proj_b     = (const float*)d_in[5];
    const float* bias_table = (const float*)d_in[6];
    const int*   rel_index  = (const int*)d_in[7];
    float* out = (float*)d_out;

    __half *x16, *qkv, *att, *wq_hi, *wp_hi;
    float* bmc;
    cudaGetSymbolAddress((void**)&x16, g_x16);
    cudaGetSymbolAddress((void**)&qkv, g_qkv);
    cudaGetSymbolAddress((void**)&att, g_att);
    cudaGetSymbolAddress((void**)&wq_hi, g_wqkv_hi);
    cudaGetSymbolAddress((void**)&wp_hi, g_wprj_hi);
    cudaGetSymbolAddress((void**)&bmc, g_bm);

    cudaFuncSetAttribute(qkv_gemm_kernel, cudaFuncAttributeMaxDynamicSharedMemorySize, GM_SMEM);
    cudaFuncSetAttribute(proj_gemm_kernel, cudaFuncAttributeMaxDynamicSharedMemorySize, GM_SMEM);

    // 0) all preps in one launch
    prep_all_kernel<<<PREP_BLOCKS, 256>>>(x, x16, qkv_w, wq_hi, proj_w, wp_hi,
                                          mask, bias_table, rel_index, bmc);
    // 1) qkv GEMM (1-term, f32 acc)
    {
        dim3 grid(QKVC / BN, MROWS / BM);
        qkv_gemm_kernel<<<grid, 256, GM_SMEM>>>(x16, wq_hi, qkv_b, qkv);
    }
    // 2) tensor-core attention (GRP=16)
    {
        dim3 grid(NWIN, HEADS, BATCH / NWIN / GRP);
        attn_mma_kernel<<<grid, 128>>>(qkv, bmc, att);
    }
    // 3) proj GEMM (1-term, f32 acc)
    {
        dim3 grid(DIMC / BN, MROWS / BM);
        proj_gemm_kernel<<<grid, 256, GM_SMEM>>>(att, wp_hi, proj_b, out);
    }
}